// round 3
// baseline (speedup 1.0000x reference)
#include <cuda_runtime.h>
#include <math.h>
#include <stdint.h>

#define NN 100000
#define EE 1600000
#define FIN 128
#define HID 64
#define FOUT 40

// ---------------- scratch (device globals) ----------------
__device__ int   g_deg[NN];
__device__ int   g_off[NN + 1];
__device__ int   g_cur[NN];
__device__ float g_dinv[NN];
__device__ int2  g_edge[EE];               // CSR-by-col: (src, w bits)
__device__ float g_h1[(size_t)NN * HID];   // x @ W1
__device__ float g_agg1[(size_t)NN * HID]; // aggregated layer-1
__device__ float g_h2[(size_t)NN * FOUT];  // relu(agg1+b1) @ W2

// ---------------- degree ----------------
__global__ void k_zero_deg() {
    int i = blockIdx.x * blockDim.x + threadIdx.x;
    if (i < NN) g_deg[i] = 0;
}

__global__ void k_count(const int* __restrict__ col) {
    int e = blockIdx.x * blockDim.x + threadIdx.x;
    if (e < EE) atomicAdd(&g_deg[col[e]], 1);
}

// ---------------- prefix scan (single block 1024 thr) + dinv ----------------
__global__ void k_scan() {
    const int CH = 98;                     // 1024*98 = 100352 >= NN
    int t = threadIdx.x;
    int base = t * CH;
    int sum = 0;
    for (int i = 0; i < CH; i++) {
        int idx = base + i;
        if (idx < NN) sum += g_deg[idx];
    }
    __shared__ int ps[1024];
    ps[t] = sum;
    __syncthreads();
    for (int o = 1; o < 1024; o <<= 1) {
        int v = (t >= o) ? ps[t - o] : 0;
        __syncthreads();
        ps[t] += v;
        __syncthreads();
    }
    int run = ps[t] - sum;                 // exclusive prefix
    for (int i = 0; i < CH; i++) {
        int idx = base + i;
        if (idx < NN) {
            int d = g_deg[idx];
            g_off[idx] = run;
            g_cur[idx] = run;
            g_dinv[idx] = rsqrtf((float)(d + 1));   // +1 self-loop
            run += d;
        }
    }
    if (t == 1023) g_off[NN] = EE;
}

// ---------------- bucket fill: CSR by destination ----------------
__global__ void k_bucket(const int* __restrict__ rows, const int* __restrict__ cols) {
    int e = blockIdx.x * blockDim.x + threadIdx.x;
    if (e >= EE) return;
    int r = rows[e];
    int c = cols[e];
    int slot = atomicAdd(&g_cur[c], 1);
    float w = g_dinv[r] * g_dinv[c];
    g_edge[slot] = make_int2(r, __float_as_int(w));
}

// ---------------- GEMM1: h1 = x @ W1 ----------------
// 128 threads, tile 64 rows x 64 cols, thread = 4 rows x 8 cols.
// x staged in smem (pad 132), W1 read via __ldg (L1-resident, 32KB).
#define XPAD 132
__global__ void k_gemm1(const float* __restrict__ x, const float* __restrict__ W) {
    __shared__ float xs[64 * XPAD];
    int t = threadIdx.x;
    int row0 = blockIdx.x * 64;
    const float4* x4 = (const float4*)x;
#pragma unroll
    for (int i = 0; i < 16; i++) {
        int f = t + i * 128;               // float4 index: 2048 total
        int r = f >> 5;
        int kq = f & 31;
        float4 v = make_float4(0.f, 0.f, 0.f, 0.f);
        if (row0 + r < NN) v = x4[(size_t)(row0 + r) * 32 + kq];
        *(float4*)&xs[r * XPAD + kq * 4] = v;
    }
    __syncthreads();

    int tx = t & 7;                        // col group of 8: cols 8*tx..8*tx+7
    int ty = t >> 3;                       // rows ty, ty+16, ty+32, ty+48
    float acc[4][8];
#pragma unroll
    for (int j = 0; j < 4; j++)
#pragma unroll
        for (int n = 0; n < 8; n++) acc[j][n] = 0.f;

    const float4* W4 = (const float4*)W;
#pragma unroll 8
    for (int k = 0; k < FIN; k++) {
        float4 b0 = __ldg(&W4[k * 16 + 2 * tx]);
        float4 b1 = __ldg(&W4[k * 16 + 2 * tx + 1]);
        float a0 = xs[ty * XPAD + k];
        float a1 = xs[(ty + 16) * XPAD + k];
        float a2 = xs[(ty + 32) * XPAD + k];
        float a3 = xs[(ty + 48) * XPAD + k];
        float av[4] = {a0, a1, a2, a3};
#pragma unroll
        for (int j = 0; j < 4; j++) {
            acc[j][0] += av[j] * b0.x; acc[j][1] += av[j] * b0.y;
            acc[j][2] += av[j] * b0.z; acc[j][3] += av[j] * b0.w;
            acc[j][4] += av[j] * b1.x; acc[j][5] += av[j] * b1.y;
            acc[j][6] += av[j] * b1.z; acc[j][7] += av[j] * b1.w;
        }
    }
#pragma unroll
    for (int j = 0; j < 4; j++) {
        int r = row0 + ty + 16 * j;
        if (r >= NN) continue;
        float4 o0 = make_float4(acc[j][0], acc[j][1], acc[j][2], acc[j][3]);
        float4 o1 = make_float4(acc[j][4], acc[j][5], acc[j][6], acc[j][7]);
        *(float4*)&g_h1[(size_t)r * HID + 8 * tx] = o0;
        *(float4*)&g_h1[(size_t)r * HID + 8 * tx + 4] = o1;
    }
}

// ---------------- layer-1 aggregation (CSR gather): 64 threads per node ----
__global__ void k_agg1() {
    int v = blockIdx.x * 4 + (threadIdx.x >> 6);
    int c = threadIdx.x & 63;
    if (v >= NN) return;
    int s = g_off[v];
    int s1 = g_off[v + 1];
    float acc = 0.f;
    for (; s + 3 < s1; s += 4) {
        int2 e0 = g_edge[s];
        int2 e1 = g_edge[s + 1];
        int2 e2 = g_edge[s + 2];
        int2 e3 = g_edge[s + 3];
        float v0 = g_h1[(size_t)e0.x * HID + c];
        float v1 = g_h1[(size_t)e1.x * HID + c];
        float v2 = g_h1[(size_t)e2.x * HID + c];
        float v3 = g_h1[(size_t)e3.x * HID + c];
        acc += __int_as_float(e0.y) * v0 + __int_as_float(e1.y) * v1;
        acc += __int_as_float(e2.y) * v2 + __int_as_float(e3.y) * v3;
    }
    for (; s < s1; s++) {
        int2 e = g_edge[s];
        acc += __int_as_float(e.y) * g_h1[(size_t)e.x * HID + c];
    }
    float d = g_dinv[v];
    acc += d * d * g_h1[(size_t)v * HID + c];      // self loop
    g_agg1[(size_t)v * HID + c] = acc;
}

// ---------------- GEMM2: h2 = relu(agg1 + b1) @ W2 ----------------
__global__ void k_gemm2(const float* __restrict__ W2, const float* __restrict__ b1) {
    __shared__ float xs[64 * 68];
    __shared__ float Ws[HID * FOUT];
    int t = threadIdx.x;
    int row0 = blockIdx.x * 64;

    for (int i = t; i < HID * FOUT; i += 256) Ws[i] = W2[i];

#pragma unroll
    for (int i = 0; i < 4; i++) {
        int f = t + i * 256;
        int r = f >> 4;
        int kq = f & 15;
        float4 v = make_float4(0.f, 0.f, 0.f, 0.f);
        if (row0 + r < NN) {
            v = *(const float4*)&g_agg1[(size_t)(row0 + r) * HID + kq * 4];
            float4 bb = *(const float4*)&b1[kq * 4];
            v.x = fmaxf(v.x + bb.x, 0.f);
            v.y = fmaxf(v.y + bb.y, 0.f);
            v.z = fmaxf(v.z + bb.z, 0.f);
            v.w = fmaxf(v.w + bb.w, 0.f);
        }
        *(float4*)&xs[r * 68 + kq * 4] = v;
    }
    __syncthreads();

    int row = t >> 2;
    int c0 = (t & 3) * 10;
    float acc[10];
#pragma unroll
    for (int j = 0; j < 10; j++) acc[j] = 0.f;
#pragma unroll 4
    for (int k = 0; k < HID; k++) {
        float a = xs[row * 68 + k];
#pragma unroll
        for (int j = 0; j < 10; j++) acc[j] += a * Ws[k * FOUT + c0 + j];
    }
    int r = row0 + row;
    if (r < NN) {
#pragma unroll
        for (int j = 0; j < 10; j++)
            g_h2[(size_t)r * FOUT + c0 + j] = acc[j];
    }
}

// ---------------- layer-2 aggregation + b2 + log_softmax (warp per node) ---
__global__ void k_agg2_lsm(float* __restrict__ out, const float* __restrict__ b2) {
    int v = (blockIdx.x * blockDim.x + threadIdx.x) >> 5;
    int lane = threadIdx.x & 31;
    if (v >= NN) return;
    int s = g_off[v];
    int s1 = g_off[v + 1];
    float a = 0.f, b = 0.f;
    for (; s + 1 < s1; s += 2) {
        int2 e0 = g_edge[s];
        int2 e1 = g_edge[s + 1];
        float w0 = __int_as_float(e0.y), w1 = __int_as_float(e1.y);
        a += w0 * g_h2[(size_t)e0.x * FOUT + lane];
        a += w1 * g_h2[(size_t)e1.x * FOUT + lane];
        if (lane < 8) {
            b += w0 * g_h2[(size_t)e0.x * FOUT + 32 + lane];
            b += w1 * g_h2[(size_t)e1.x * FOUT + 32 + lane];
        }
    }
    if (s < s1) {
        int2 e = g_edge[s];
        float w = __int_as_float(e.y);
        a += w * g_h2[(size_t)e.x * FOUT + lane];
        if (lane < 8) b += w * g_h2[(size_t)e.x * FOUT + 32 + lane];
    }
    float d = g_dinv[v];
    float d2 = d * d;
    a += d2 * g_h2[(size_t)v * FOUT + lane];
    if (lane < 8) b += d2 * g_h2[(size_t)v * FOUT + 32 + lane];

    a += __ldg(&b2[lane]);
    float bb = (lane < 8) ? (b + __ldg(&b2[32 + lane])) : -INFINITY;

    float m = fmaxf(a, bb);
#pragma unroll
    for (int o = 16; o; o >>= 1) m = fmaxf(m, __shfl_xor_sync(0xffffffffu, m, o));
    float sum = expf(a - m) + ((lane < 8) ? expf(bb - m) : 0.f);
#pragma unroll
    for (int o = 16; o; o >>= 1) sum += __shfl_xor_sync(0xffffffffu, sum, o);
    float lse = m + logf(sum);

    float* p = out + (size_t)v * FOUT;
    p[lane] = a - lse;
    if (lane < 8) p[32 + lane] = bb - lse;
}

// ---------------- launcher ----------------
extern "C" void kernel_launch(void* const* d_in, const int* in_sizes, int n_in,
                              void* d_out, int out_size) {
    const float* x  = (const float*)d_in[0];
    const int*   ei = (const int*)d_in[1];
    const float* W1 = (const float*)d_in[2];
    const float* b1 = (const float*)d_in[3];
    const float* W2 = (const float*)d_in[4];
    const float* b2 = (const float*)d_in[5];
    float* out = (float*)d_out;
    const int* rows = ei;
    const int* cols = ei + EE;

    k_zero_deg<<<(NN + 255) / 256, 256>>>();
    k_count<<<(EE + 255) / 256, 256>>>(cols);
    k_scan<<<1, 1024>>>();
    k_bucket<<<(EE + 255) / 256, 256>>>(rows, cols);

    k_gemm1<<<(NN + 63) / 64, 128>>>(x, W1);
    k_agg1<<<(NN + 3) / 4, 256>>>();

    k_gemm2<<<(NN + 63) / 64, 256>>>(W2, b1);
    k_agg2_lsm<<<(NN * 32 + 255) / 256, 256>>>(out, b2);
}

// round 4
// speedup vs baseline: 1.7245x; 1.7245x over previous
#include <cuda_runtime.h>
#include <math.h>
#include <stdint.h>

#define NN 100000
#define EE 1600000
#define FIN 128
#define HID 64
#define FOUT 40
#define NB 391                  // ceil(NN/256) scan blocks

// ---------------- scratch (device globals) ----------------
__device__ int   g_deg[NN];
__device__ int   g_off[NN + 1];
__device__ int   g_cur[NN];
__device__ int   g_bsum[NB];
__device__ float g_dinv[NN];
__device__ int2  g_edge[EE];               // CSR-by-col: (src, w bits)
__device__ float g_h1[(size_t)NN * HID];   // x @ W1
__device__ float g_agg1[(size_t)NN * HID]; // aggregated layer-1
__device__ float g_h2[(size_t)NN * FOUT];  // relu(agg1+b1) @ W2

// ---------------- degree ----------------
__global__ void k_zero_deg() {
    int i = blockIdx.x * blockDim.x + threadIdx.x;
    if (i < NN) g_deg[i] = 0;
}

__global__ void k_count(const int* __restrict__ col) {
    int e = blockIdx.x * blockDim.x + threadIdx.x;
    if (e < EE) atomicAdd(&g_deg[col[e]], 1);
}

// ---------------- coalesced 3-phase exclusive scan ----------------
// phase 1: per-block (256-wide) sums
__global__ void k_scan1() {
    __shared__ int ws[8];
    int i = blockIdx.x * 256 + threadIdx.x;
    int d = (i < NN) ? g_deg[i] : 0;
    int s = d;
#pragma unroll
    for (int o = 16; o; o >>= 1) s += __shfl_xor_sync(0xffffffffu, s, o);
    if ((threadIdx.x & 31) == 0) ws[threadIdx.x >> 5] = s;
    __syncthreads();
    if (threadIdx.x == 0) {
        int t = 0;
#pragma unroll
        for (int w = 0; w < 8; w++) t += ws[w];
        g_bsum[blockIdx.x] = t;
    }
}

// phase 2: scan the 391 block sums (one block)
__global__ void k_scan2() {
    __shared__ int ps[512];
    int t = threadIdx.x;
    int v = (t < NB) ? g_bsum[t] : 0;
    ps[t] = v;
    __syncthreads();
    for (int o = 1; o < 512; o <<= 1) {
        int u = (t >= o) ? ps[t - o] : 0;
        __syncthreads();
        ps[t] += u;
        __syncthreads();
    }
    if (t < NB) g_bsum[t] = ps[t] - v;      // exclusive
    if (t == 0) g_off[NN] = EE;
}

// phase 3: intra-block scan + offsets + dinv
__global__ void k_scan3() {
    __shared__ int ps[256];
    int t = threadIdx.x;
    int i = blockIdx.x * 256 + t;
    int d = (i < NN) ? g_deg[i] : 0;
    ps[t] = d;
    __syncthreads();
    for (int o = 1; o < 256; o <<= 1) {
        int u = (t >= o) ? ps[t - o] : 0;
        __syncthreads();
        ps[t] += u;
        __syncthreads();
    }
    if (i < NN) {
        int off = g_bsum[blockIdx.x] + ps[t] - d;   // exclusive
        g_off[i] = off;
        g_cur[i] = off;
        g_dinv[i] = rsqrtf((float)(d + 1));         // +1 self-loop
    }
}

// ---------------- bucket fill: CSR by destination ----------------
__global__ void k_bucket(const int* __restrict__ rows, const int* __restrict__ cols) {
    int e = blockIdx.x * blockDim.x + threadIdx.x;
    if (e >= EE) return;
    int r = rows[e];
    int c = cols[e];
    int slot = atomicAdd(&g_cur[c], 1);
    float w = g_dinv[r] * g_dinv[c];
    g_edge[slot] = make_int2(r, __float_as_int(w));
}

// ---------------- GEMM1: h1 = x @ W1 ----------------
#define XPAD 132
__global__ void k_gemm1(const float* __restrict__ x, const float* __restrict__ W) {
    __shared__ float xs[64 * XPAD];
    int t = threadIdx.x;
    int row0 = blockIdx.x * 64;
    const float4* x4 = (const float4*)x;
#pragma unroll
    for (int i = 0; i < 16; i++) {
        int f = t + i * 128;
        int r = f >> 5;
        int kq = f & 31;
        float4 v = make_float4(0.f, 0.f, 0.f, 0.f);
        if (row0 + r < NN) v = x4[(size_t)(row0 + r) * 32 + kq];
        *(float4*)&xs[r * XPAD + kq * 4] = v;
    }
    __syncthreads();

    int tx = t & 7;
    int ty = t >> 3;
    float acc[4][8];
#pragma unroll
    for (int j = 0; j < 4; j++)
#pragma unroll
        for (int n = 0; n < 8; n++) acc[j][n] = 0.f;

    const float4* W4 = (const float4*)W;
#pragma unroll 8
    for (int k = 0; k < FIN; k++) {
        float4 b0 = __ldg(&W4[k * 16 + 2 * tx]);
        float4 b1 = __ldg(&W4[k * 16 + 2 * tx + 1]);
        float av[4] = {xs[ty * XPAD + k], xs[(ty + 16) * XPAD + k],
                       xs[(ty + 32) * XPAD + k], xs[(ty + 48) * XPAD + k]};
#pragma unroll
        for (int j = 0; j < 4; j++) {
            acc[j][0] += av[j] * b0.x; acc[j][1] += av[j] * b0.y;
            acc[j][2] += av[j] * b0.z; acc[j][3] += av[j] * b0.w;
            acc[j][4] += av[j] * b1.x; acc[j][5] += av[j] * b1.y;
            acc[j][6] += av[j] * b1.z; acc[j][7] += av[j] * b1.w;
        }
    }
#pragma unroll
    for (int j = 0; j < 4; j++) {
        int r = row0 + ty + 16 * j;
        if (r >= NN) continue;
        float4 o0 = make_float4(acc[j][0], acc[j][1], acc[j][2], acc[j][3]);
        float4 o1 = make_float4(acc[j][4], acc[j][5], acc[j][6], acc[j][7]);
        *(float4*)&g_h1[(size_t)r * HID + 8 * tx] = o0;
        *(float4*)&g_h1[(size_t)r * HID + 8 * tx + 4] = o1;
    }
}

// ---------------- layer-1 aggregation (CSR gather): 64 threads per node ----
__global__ void k_agg1() {
    int v = blockIdx.x * 4 + (threadIdx.x >> 6);
    int c = threadIdx.x & 63;
    if (v >= NN) return;
    int s = g_off[v];
    int s1 = g_off[v + 1];
    float acc = 0.f;
    for (; s + 3 < s1; s += 4) {
        int2 e0 = g_edge[s];
        int2 e1 = g_edge[s + 1];
        int2 e2 = g_edge[s + 2];
        int2 e3 = g_edge[s + 3];
        float v0 = g_h1[(size_t)e0.x * HID + c];
        float v1 = g_h1[(size_t)e1.x * HID + c];
        float v2 = g_h1[(size_t)e2.x * HID + c];
        float v3 = g_h1[(size_t)e3.x * HID + c];
        acc += __int_as_float(e0.y) * v0 + __int_as_float(e1.y) * v1;
        acc += __int_as_float(e2.y) * v2 + __int_as_float(e3.y) * v3;
    }
    for (; s < s1; s++) {
        int2 e = g_edge[s];
        acc += __int_as_float(e.y) * g_h1[(size_t)e.x * HID + c];
    }
    float d = g_dinv[v];
    acc += d * d * g_h1[(size_t)v * HID + c];      // self loop
    g_agg1[(size_t)v * HID + c] = acc;
}

// ---------------- GEMM2: h2 = relu(agg1 + b1) @ W2 ----------------
__global__ void k_gemm2(const float* __restrict__ W2, const float* __restrict__ b1) {
    __shared__ float xs[64 * 68];
    __shared__ float Ws[HID * FOUT];
    int t = threadIdx.x;
    int row0 = blockIdx.x * 64;

    for (int i = t; i < HID * FOUT; i += 256) Ws[i] = W2[i];

#pragma unroll
    for (int i = 0; i < 4; i++) {
        int f = t + i * 256;
        int r = f >> 4;
        int kq = f & 15;
        float4 v = make_float4(0.f, 0.f, 0.f, 0.f);
        if (row0 + r < NN) {
            v = *(const float4*)&g_agg1[(size_t)(row0 + r) * HID + kq * 4];
            float4 bb = *(const float4*)&b1[kq * 4];
            v.x = fmaxf(v.x + bb.x, 0.f);
            v.y = fmaxf(v.y + bb.y, 0.f);
            v.z = fmaxf(v.z + bb.z, 0.f);
            v.w = fmaxf(v.w + bb.w, 0.f);
        }
        *(float4*)&xs[r * 68 + kq * 4] = v;
    }
    __syncthreads();

    int row = t >> 2;
    int c0 = (t & 3) * 10;
    float acc[10];
#pragma unroll
    for (int j = 0; j < 10; j++) acc[j] = 0.f;
#pragma unroll 4
    for (int k = 0; k < HID; k++) {
        float a = xs[row * 68 + k];
#pragma unroll
        for (int j = 0; j < 10; j++) acc[j] += a * Ws[k * FOUT + c0 + j];
    }
    int r = row0 + row;
    if (r < NN) {
#pragma unroll
        for (int j = 0; j < 10; j++)
            g_h2[(size_t)r * FOUT + c0 + j] = acc[j];
    }
}

// ---------------- layer-2 aggregation + b2 + log_softmax (warp per node) ---
__global__ void k_agg2_lsm(float* __restrict__ out, const float* __restrict__ b2) {
    int v = (blockIdx.x * blockDim.x + threadIdx.x) >> 5;
    int lane = threadIdx.x & 31;
    if (v >= NN) return;
    int s = g_off[v];
    int s1 = g_off[v + 1];
    float a = 0.f, b = 0.f;
    for (; s + 1 < s1; s += 2) {
        int2 e0 = g_edge[s];
        int2 e1 = g_edge[s + 1];
        float w0 = __int_as_float(e0.y), w1 = __int_as_float(e1.y);
        a += w0 * g_h2[(size_t)e0.x * FOUT + lane];
        a += w1 * g_h2[(size_t)e1.x * FOUT + lane];
        if (lane < 8) {
            b += w0 * g_h2[(size_t)e0.x * FOUT + 32 + lane];
            b += w1 * g_h2[(size_t)e1.x * FOUT + 32 + lane];
        }
    }
    if (s < s1) {
        int2 e = g_edge[s];
        float w = __int_as_float(e.y);
        a += w * g_h2[(size_t)e.x * FOUT + lane];
        if (lane < 8) b += w * g_h2[(size_t)e.x * FOUT + 32 + lane];
    }
    float d = g_dinv[v];
    float d2 = d * d;
    a += d2 * g_h2[(size_t)v * FOUT + lane];
    if (lane < 8) b += d2 * g_h2[(size_t)v * FOUT + 32 + lane];

    a += __ldg(&b2[lane]);
    float bb = (lane < 8) ? (b + __ldg(&b2[32 + lane])) : -INFINITY;

    float m = fmaxf(a, bb);
#pragma unroll
    for (int o = 16; o; o >>= 1) m = fmaxf(m, __shfl_xor_sync(0xffffffffu, m, o));
    float sum = expf(a - m) + ((lane < 8) ? expf(bb - m) : 0.f);
#pragma unroll
    for (int o = 16; o; o >>= 1) sum += __shfl_xor_sync(0xffffffffu, sum, o);
    float lse = m + logf(sum);

    float* p = out + (size_t)v * FOUT;
    p[lane] = a - lse;
    if (lane < 8) p[32 + lane] = bb - lse;
}

// ---------------- launcher ----------------
extern "C" void kernel_launch(void* const* d_in, const int* in_sizes, int n_in,
                              void* d_out, int out_size) {
    const float* x  = (const float*)d_in[0];
    const int*   ei = (const int*)d_in[1];
    const float* W1 = (const float*)d_in[2];
    const float* b1 = (const float*)d_in[3];
    const float* W2 = (const float*)d_in[4];
    const float* b2 = (const float*)d_in[5];
    float* out = (float*)d_out;
    const int* rows = ei;
    const int* cols = ei + EE;

    k_zero_deg<<<(NN + 255) / 256, 256>>>();
    k_count<<<(EE + 255) / 256, 256>>>(cols);
    k_scan1<<<NB, 256>>>();
    k_scan2<<<1, 512>>>();
    k_scan3<<<NB, 256>>>();
    k_bucket<<<(EE + 255) / 256, 256>>>(rows, cols);

    k_gemm1<<<(NN + 63) / 64, 128>>>(x, W1);
    k_agg1<<<(NN + 3) / 4, 256>>>();

    k_gemm2<<<(NN + 63) / 64, 256>>>(W2, b1);
    k_agg2_lsm<<<(NN * 32 + 255) / 256, 256>>>(out, b2);
}

// round 6
// speedup vs baseline: 2.0236x; 1.1735x over previous
#include <cuda_runtime.h>
#include <cuda_fp16.h>
#include <math.h>
#include <stdint.h>

#define NN 100000
#define EE 1600000
#define FIN 128
#define HID 64
#define FOUT 40
#define H2P 64                  // padded h2 row (halves) -> 128B rows
#define NB 391                  // ceil(NN/256) scan blocks

// ---------------- scratch (device globals) ----------------
__device__ int    g_deg[NN];
__device__ int    g_off[NN + 1];
__device__ int    g_cur[NN];
__device__ int    g_bsum[NB];
__device__ float  g_dinv[NN];
__device__ int2   g_edge[EE];               // CSR-by-col: (src, w bits)
__device__ __half g_h1h[(size_t)NN * HID];  // x @ W1, fp16
__device__ float  g_agg1[(size_t)NN * HID]; // aggregated layer-1, fp32
__device__ __half g_h2h[(size_t)NN * H2P];  // relu(agg1+b1) @ W2, fp16 padded

// ---------------- degree ----------------
__global__ void k_zero_deg() {
    int i = blockIdx.x * blockDim.x + threadIdx.x;
    if (i < NN) g_deg[i] = 0;
}

__global__ void k_count(const int* __restrict__ col) {
    int e = blockIdx.x * blockDim.x + threadIdx.x;
    if (e < EE) atomicAdd(&g_deg[col[e]], 1);
}

// ---------------- coalesced 3-phase exclusive scan ----------------
__global__ void k_scan1() {
    __shared__ int ws[8];
    int i = blockIdx.x * 256 + threadIdx.x;
    int d = (i < NN) ? g_deg[i] : 0;
    int s = d;
#pragma unroll
    for (int o = 16; o; o >>= 1) s += __shfl_xor_sync(0xffffffffu, s, o);
    if ((threadIdx.x & 31) == 0) ws[threadIdx.x >> 5] = s;
    __syncthreads();
    if (threadIdx.x == 0) {
        int t = 0;
#pragma unroll
        for (int w = 0; w < 8; w++) t += ws[w];
        g_bsum[blockIdx.x] = t;
    }
}

__global__ void k_scan2() {
    __shared__ int ps[512];
    int t = threadIdx.x;
    int v = (t < NB) ? g_bsum[t] : 0;
    ps[t] = v;
    __syncthreads();
    for (int o = 1; o < 512; o <<= 1) {
        int u = (t >= o) ? ps[t - o] : 0;
        __syncthreads();
        ps[t] += u;
        __syncthreads();
    }
    if (t < NB) g_bsum[t] = ps[t] - v;
    if (t == 0) g_off[NN] = EE;
}

__global__ void k_scan3() {
    __shared__ int ps[256];
    int t = threadIdx.x;
    int i = blockIdx.x * 256 + t;
    int d = (i < NN) ? g_deg[i] : 0;
    ps[t] = d;
    __syncthreads();
    for (int o = 1; o < 256; o <<= 1) {
        int u = (t >= o) ? ps[t - o] : 0;
        __syncthreads();
        ps[t] += u;
        __syncthreads();
    }
    if (i < NN) {
        int off = g_bsum[blockIdx.x] + ps[t] - d;
        g_off[i] = off;
        g_cur[i] = off;
        g_dinv[i] = rsqrtf((float)(d + 1));         // +1 self-loop
    }
}

// ---------------- bucket fill: CSR by destination ----------------
__global__ void k_bucket(const int* __restrict__ rows, const int* __restrict__ cols) {
    int e = blockIdx.x * blockDim.x + threadIdx.x;
    if (e >= EE) return;
    int r = rows[e];
    int c = cols[e];
    int slot = atomicAdd(&g_cur[c], 1);
    float w = g_dinv[r] * g_dinv[c];
    g_edge[slot] = make_int2(r, __float_as_int(w));
}

// ---------------- GEMM1: h1 = x @ W1 (fp32 math, fp16 store) ----------------
#define XPAD 132
__global__ void k_gemm1(const float* __restrict__ x, const float* __restrict__ W) {
    __shared__ float xs[64 * XPAD];
    int t = threadIdx.x;
    int row0 = blockIdx.x * 64;
    const float4* x4 = (const float4*)x;
#pragma unroll
    for (int i = 0; i < 16; i++) {
        int f = t + i * 128;
        int r = f >> 5;
        int kq = f & 31;
        float4 v = make_float4(0.f, 0.f, 0.f, 0.f);
        if (row0 + r < NN) v = x4[(size_t)(row0 + r) * 32 + kq];
        *(float4*)&xs[r * XPAD + kq * 4] = v;
    }
    __syncthreads();

    int tx = t & 7;
    int ty = t >> 3;
    float acc[4][8];
#pragma unroll
    for (int j = 0; j < 4; j++)
#pragma unroll
        for (int n = 0; n < 8; n++) acc[j][n] = 0.f;

    const float4* W4 = (const float4*)W;
#pragma unroll 8
    for (int k = 0; k < FIN; k++) {
        float4 b0 = __ldg(&W4[k * 16 + 2 * tx]);
        float4 b1 = __ldg(&W4[k * 16 + 2 * tx + 1]);
        float av[4] = {xs[ty * XPAD + k], xs[(ty + 16) * XPAD + k],
                       xs[(ty + 32) * XPAD + k], xs[(ty + 48) * XPAD + k]};
#pragma unroll
        for (int j = 0; j < 4; j++) {
            acc[j][0] += av[j] * b0.x; acc[j][1] += av[j] * b0.y;
            acc[j][2] += av[j] * b0.z; acc[j][3] += av[j] * b0.w;
            acc[j][4] += av[j] * b1.x; acc[j][5] += av[j] * b1.y;
            acc[j][6] += av[j] * b1.z; acc[j][7] += av[j] * b1.w;
        }
    }
#pragma unroll
    for (int j = 0; j < 4; j++) {
        int r = row0 + ty + 16 * j;
        if (r >= NN) continue;
        __half2* dst = (__half2*)&g_h1h[(size_t)r * HID] + 4 * tx;
        dst[0] = __floats2half2_rn(acc[j][0], acc[j][1]);
        dst[1] = __floats2half2_rn(acc[j][2], acc[j][3]);
        dst[2] = __floats2half2_rn(acc[j][4], acc[j][5]);
        dst[3] = __floats2half2_rn(acc[j][6], acc[j][7]);
    }
}

// ---------------- layer-1 aggregation: warp per node, half2 gathers --------
__global__ void k_agg1() {
    int v = blockIdx.x * 8 + (threadIdx.x >> 5);
    int lane = threadIdx.x & 31;
    if (v >= NN) return;
    int s = g_off[v];
    int s1 = g_off[v + 1];
    const __half2* H = (const __half2*)g_h1h;   // 32 half2 per row
    float ax = 0.f, ay = 0.f;
    for (; s + 3 < s1; s += 4) {
        int2 e0 = g_edge[s];
        int2 e1 = g_edge[s + 1];
        int2 e2 = g_edge[s + 2];
        int2 e3 = g_edge[s + 3];
        float2 f0 = __half22float2(H[(size_t)e0.x * 32 + lane]);
        float2 f1 = __half22float2(H[(size_t)e1.x * 32 + lane]);
        float2 f2 = __half22float2(H[(size_t)e2.x * 32 + lane]);
        float2 f3 = __half22float2(H[(size_t)e3.x * 32 + lane]);
        float w0 = __int_as_float(e0.y), w1 = __int_as_float(e1.y);
        float w2 = __int_as_float(e2.y), w3 = __int_as_float(e3.y);
        ax += w0 * f0.x + w1 * f1.x + w2 * f2.x + w3 * f3.x;
        ay += w0 * f0.y + w1 * f1.y + w2 * f2.y + w3 * f3.y;
    }
    for (; s < s1; s++) {
        int2 e = g_edge[s];
        float2 f = __half22float2(H[(size_t)e.x * 32 + lane]);
        float w = __int_as_float(e.y);
        ax += w * f.x;
        ay += w * f.y;
    }
    float d = g_dinv[v];
    float2 sv = __half22float2(H[(size_t)v * 32 + lane]);
    ax += d * d * sv.x;
    ay += d * d * sv.y;
    *(float2*)&g_agg1[(size_t)v * HID + 2 * lane] = make_float2(ax, ay);
}

// ---------------- GEMM2: h2 = relu(agg1 + b1) @ W2 (fp16 store, padded) ----
__global__ void k_gemm2(const float* __restrict__ W2, const float* __restrict__ b1) {
    __shared__ float xs[64 * 68];
    __shared__ float Ws[HID * FOUT];
    int t = threadIdx.x;
    int row0 = blockIdx.x * 64;

    for (int i = t; i < HID * FOUT; i += 256) Ws[i] = W2[i];

#pragma unroll
    for (int i = 0; i < 4; i++) {
        int f = t + i * 256;
        int r = f >> 4;
        int kq = f & 15;
        float4 v = make_float4(0.f, 0.f, 0.f, 0.f);
        if (row0 + r < NN) {
            v = *(const float4*)&g_agg1[(size_t)(row0 + r) * HID + kq * 4];
            float4 bb = *(const float4*)&b1[kq * 4];
            v.x = fmaxf(v.x + bb.x, 0.f);
            v.y = fmaxf(v.y + bb.y, 0.f);
            v.z = fmaxf(v.z + bb.z, 0.f);
            v.w = fmaxf(v.w + bb.w, 0.f);
        }
        *(float4*)&xs[r * 68 + kq * 4] = v;
    }
    __syncthreads();

    int row = t >> 2;
    int c0 = (t & 3) * 10;
    float acc[10];
#pragma unroll
    for (int j = 0; j < 10; j++) acc[j] = 0.f;
#pragma unroll 4
    for (int k = 0; k < HID; k++) {
        float a = xs[row * 68 + k];
#pragma unroll
        for (int j = 0; j < 10; j++) acc[j] += a * Ws[k * FOUT + c0 + j];
    }
    int r = row0 + row;
    if (r < NN) {
#pragma unroll
        for (int j = 0; j < 10; j++)
            g_h2h[(size_t)r * H2P + c0 + j] = __float2half_rn(acc[j]);
    }
}

// ---------------- layer-2 aggregation + b2 + log_softmax (warp per node) ---
__global__ void k_agg2_lsm(float* __restrict__ out, const float* __restrict__ b2) {
    int v = (blockIdx.x * blockDim.x + threadIdx.x) >> 5;
    int lane = threadIdx.x & 31;
    if (v >= NN) return;
    bool act = lane < 20;                        // lanes cover cols 2l, 2l+1
    int s = g_off[v];
    int s1 = g_off[v + 1];
    const __half2* H = (const __half2*)g_h2h;    // 32 half2 per padded row
    float ax = 0.f, ay = 0.f;
    for (; s + 3 < s1; s += 4) {
        int2 e0 = g_edge[s];
        int2 e1 = g_edge[s + 1];
        int2 e2 = g_edge[s + 2];
        int2 e3 = g_edge[s + 3];
        if (act) {
            float2 f0 = __half22float2(H[(size_t)e0.x * 32 + lane]);
            float2 f1 = __half22float2(H[(size_t)e1.x * 32 + lane]);
            float2 f2 = __half22float2(H[(size_t)e2.x * 32 + lane]);
            float2 f3 = __half22float2(H[(size_t)e3.x * 32 + lane]);
            float w0 = __int_as_float(e0.y), w1 = __int_as_float(e1.y);
            float w2 = __int_as_float(e2.y), w3 = __int_as_float(e3.y);
            ax += w0 * f0.x + w1 * f1.x + w2 * f2.x + w3 * f3.x;
            ay += w0 * f0.y + w1 * f1.y + w2 * f2.y + w3 * f3.y;
        }
    }
    for (; s < s1; s++) {
        int2 e = g_edge[s];
        if (act) {
            float2 f = __half22float2(H[(size_t)e.x * 32 + lane]);
            float w = __int_as_float(e.y);
            ax += w * f.x;
            ay += w * f.y;
        }
    }
    float d = g_dinv[v];
    float d2 = d * d;
    if (act) {
        float2 sv = __half22float2(H[(size_t)v * 32 + lane]);
        ax += d2 * sv.x;
        ay += d2 * sv.y;
        ax += __ldg(&b2[2 * lane]);
        ay += __ldg(&b2[2 * lane + 1]);
    }
    float m = act ? fmaxf(ax, ay) : -INFINITY;
#pragma unroll
    for (int o = 16; o; o >>= 1) m = fmaxf(m, __shfl_xor_sync(0xffffffffu, m, o));
    float sum = act ? (expf(ax - m) + expf(ay - m)) : 0.f;
#pragma unroll
    for (int o = 16; o; o >>= 1) sum += __shfl_xor_sync(0xffffffffu, sum, o);
    float lse = m + logf(sum);
    if (act)
        *(float2*)&out[(size_t)v * FOUT + 2 * lane] = make_float2(ax - lse, ay - lse);
}

// ---------------- launcher (gemm1 in profiled slot #4) ----------------
extern "C" void kernel_launch(void* const* d_in, const int* in_sizes, int n_in,
                              void* d_out, int out_size) {
    const float* x  = (const float*)d_in[0];
    const int*   ei = (const int*)d_in[1];
    const float* W1 = (const float*)d_in[2];
    const float* b1 = (const float*)d_in[3];
    const float* W2 = (const float*)d_in[4];
    const float* b2 = (const float*)d_in[5];
    float* out = (float*)d_out;
    const int* rows = ei;
    const int* cols = ei + EE;

    k_zero_deg<<<(NN + 255) / 256, 256>>>();
    k_count<<<(EE + 255) / 256, 256>>>(cols);
    k_scan1<<<NB, 256>>>();
    k_gemm1<<<(NN + 63) / 64, 128>>>(x, W1);    // slot 4: gets profiled
    k_scan2<<<1, 512>>>();
    k_scan3<<<NB, 256>>>();
    k_bucket<<<(EE + 255) / 256, 256>>>(rows, cols);

    k_agg1<<<(NN + 7) / 8, 256>>>();
    k_gemm2<<<(NN + 63) / 64, 256>>>(W2, b1);
    k_agg2_lsm<<<(NN * 32 + 255) / 256, 256>>>(out, b2);
}